// round 13
// baseline (speedup 1.0000x reference)
#include <cuda_runtime.h>
#include <cuda_fp16.h>
#include <math.h>
#include <stdint.h>

// ---------------------------------------------------------------------------
// ConvKAN as conv3x3-GEMM over expanded features (silu + 6 cubic B-spline
// bases), fp16 inputs, fp32 accumulation.
//   M = 32768 pixels, N = 128 outputs, K = 9*448 = 4032
// GEMM: mma.sync.m16n8k16 + ldmatrix.x4 (SW128 swizzle) + cp.async.cg,
//   3-stage pipeline, CTA tile 256x128 (halves LDS bytes/MAC vs 128x128),
//   1 CTA/SM, balanced split-K over 148 CTAs, red.global.add combine.
// ---------------------------------------------------------------------------

#define B_      8
#define H_      64
#define W_      64
#define CIN     64
#define COUT    128
#define FEAT    7
#define CEXP    (CIN*FEAT)   // 448
#define HP      (H_+2)
#define WP      (W_+2)
#define KTOT    (9*CEXP)     // 4032
#define BKH     64           // halves per K-tile (128B rows)
#define NCH     (CEXP/BKH)   // 7 chunks per tap
#define NIT     (9*NCH)      // 63 K-tiles per output tile
#define NTILE   128          // output tiles (256 pixels x 128 outputs)
#define NCTA    148          // 1 CTA per SM, one wave
#define NU      (NTILE*NIT)  // 8064 work units

__device__ __align__(128) __half g_A[(size_t)B_*HP*WP*CEXP];  // expanded (halo=f(0))
__device__ __align__(128) __half g_Wt[(size_t)COUT*KTOT];     // packed weights [o][k]

__device__ __forceinline__ uint32_t smem_u32(const void* p) {
    uint32_t a;
    asm("{ .reg .u64 t; cvta.to.shared.u64 t, %1; cvt.u32.u64 %0, t; }"
        : "=r"(a) : "l"(p));
    return a;
}
#define CP_ASYNC16(dst, src) \
    asm volatile("cp.async.cg.shared.global [%0], [%1], 16;" :: "r"(dst), "l"(src))
#define CP_COMMIT() asm volatile("cp.async.commit_group;" ::: "memory")
#define CP_WAIT(n)  asm volatile("cp.async.wait_group %0;" :: "n"(n) : "memory")
#define LDSM_X4(r, a) \
    asm volatile("ldmatrix.sync.aligned.m8n8.x4.shared.b16 {%0,%1,%2,%3}, [%4];" \
        : "=r"((r)[0]), "=r"((r)[1]), "=r"((r)[2]), "=r"((r)[3]) : "r"(a))
#define RED_ADD_F32(p, v) \
    asm volatile("red.global.add.f32 [%0], %1;" :: "l"(p), "f"(v) : "memory")

// ---------------------------------------------------------------------------
// Kernel 1 (fused): [0,NEXP) expand x->A; [NEXP,+NWPK) pack W; rest zero out.
// ---------------------------------------------------------------------------
#define NEXP  ((B_*HP*WP)/4)                 // 8712 expand blocks
#define NWPK  ((COUT*KTOT + 255)/256)        // 2016 wpack blocks
#define NZERO ((32768*COUT/4)/256)           // 4096 zero blocks (float4 each)

__global__ __launch_bounds__(256) void prep_kernel(
        const float* __restrict__ x,
        const float* __restrict__ base_w,
        const float* __restrict__ spline_w,
        float* __restrict__ out) {
    if (blockIdx.x >= NEXP + NWPK) {
        int idx = (blockIdx.x - NEXP - NWPK) * 256 + threadIdx.x;
        ((float4*)out)[idx] = make_float4(0.f, 0.f, 0.f, 0.f);
        return;
    }
    if (blockIdx.x >= NEXP) {
        // ---- weight pack: g_Wt[o][k], k = tap*448 + c*7 + t, i = c*9 + tap
        int idx = (blockIdx.x - NEXP) * 256 + threadIdx.x;
        if (idx >= COUT*KTOT) return;
        int o = idx / KTOT;
        int k = idx - o * KTOT;
        int tap = k / CEXP;
        int cc  = k - tap * CEXP;
        int c   = cc / FEAT;
        int t   = cc - c * FEAT;
        int i   = c * 9 + tap;
        float w = (t == 0) ? base_w[(size_t)o * 576 + i]
                           : spline_w[((size_t)o * 576 + i) * 6 + (t - 1)];
        g_Wt[idx] = __float2half_rn(w);
        return;
    }

    __shared__ __half st[4*CEXP];
    int t = threadIdx.x;
    int p = t >> 6, c = t & 63;
    int pix = blockIdx.x * 4 + p;
    int wp  = pix % WP;
    int t1  = pix / WP;
    int hp  = t1 % HP;
    int n   = t1 / HP;

    bool halo = (hp == 0 || hp == HP-1 || wp == 0 || wp == WP-1);
    float v = halo ? 0.0f
                   : x[(((size_t)n * H_ + (hp-1)) * W_ + (wp-1)) * CIN + c];

    float s = v / (1.0f + __expf(-v));

    __half* d = st + p * CEXP + c * FEAT;
    d[0] = __float2half_rn(s);
    d[1] = __half(0.0f); d[2] = __half(0.0f); d[3] = __half(0.0f);
    d[4] = __half(0.0f); d[5] = __half(0.0f); d[6] = __half(0.0f);

    // uniform cubic B-spline: interval j = floor((v+3)*1.5) in [0,8],
    // pieces n0..n3 -> basis slots m = j-3..j, clipped to [0,5].
    float tpos = (v + 3.0f) * 1.5f;
    float fj = floorf(tpos);
    int j = (int)fj;
    if (j >= 0 && j <= 8) {
        float u  = tpos - fj;
        float um = 1.0f - u;
        float u2 = u*u, u3 = u2*u;
        const float k6 = 1.0f/6.0f;
        float n0 = um*um*um*k6;
        float n1 = (3.0f*u3 - 6.0f*u2 + 4.0f)*k6;
        float n2 = (-3.0f*u3 + 3.0f*u2 + 3.0f*u + 1.0f)*k6;
        float n3 = u3*k6;
        int m0 = j - 3;
        if (m0     >= 0 && m0     < 6) d[1 + m0] = __float2half_rn(n0);
        if (m0 + 1 >= 0 && m0 + 1 < 6) d[2 + m0] = __float2half_rn(n1);
        if (m0 + 2 >= 0 && m0 + 2 < 6) d[3 + m0] = __float2half_rn(n2);
        if (m0 + 3 >= 0 && m0 + 3 < 6) d[4 + m0] = __float2half_rn(n3);
    }
    __syncthreads();

    const uint4* s4 = (const uint4*)st;
    uint4* d4 = (uint4*)(g_A + (size_t)blockIdx.x * 4 * CEXP);
    if (t < 224) d4[t] = s4[t];   // 4*448 halves = 224 uint4
}

// ---------------------------------------------------------------------------
// Kernel 2: fp16 HMMA GEMM, BM=256 x BN=128 x BK=64, balanced split-K.
// smem: 3 stages x 48KB (A 32KB @+0, B 16KB @+32K). SW128 swizzle rows.
// 8 warps = 4(m) x 2(n), warp tile 64x64 (4x8 m16n8k16 per kk).
// Single barrier per K-tile:
//   wait(own tile-kt) -> __syncthreads -> issue kt+2 -> compute kt.
// Prologue commits exactly 2 groups (2nd may be empty); loop commits exactly
// one (maybe empty) per iteration -> CP_WAIT(1) == "tile kt landed".
// ---------------------------------------------------------------------------
#define STGB    49152
#define STG(s)  ((s)*STGB)
#define SMEM_TOTAL (3*STGB)   // 144 KB

__global__ __launch_bounds__(256, 1) void convkan_hmma(
        const float* __restrict__ bias, float* __restrict__ out) {
    extern __shared__ char smem[];
    const uint32_t sb = smem_u32(smem);

    const int bid  = blockIdx.x;          // 0..147
    const int tid  = threadIdx.x;
    const int warp = tid >> 5;
    const int lane = tid & 31;
    const int gid  = lane >> 2;
    const int tig  = lane & 3;
    const int wm   = (warp & 3) * 64;     // 4 m-warps
    const int wn   = (warp >> 2) * 64;    // 2 n-warps

    // ---- loader algebra: thread handles 16B unit f = tid&7 of rows
    // r0 + 32*i (A: i=0..7 -> rows 0..255, B: i=0..3 -> rows 0..127).
    const int fA = tid & 7;
    const int r0 = tid >> 3;              // 0..31
    // swizzled smem column offset is row-invariant across i (32*i ≡ 0 mod 8):
    const uint32_t swcol = ((uint32_t)(fA ^ (r0 & 7))) << 4;
    const uint32_t ldstA = sb + (uint32_t)r0 * 128 + swcol;      // + i*4096
    const uint32_t ldstB = ldstA + 32768;                        // + i*4096
    // A global: row = r0 + 32*i -> hl = i>>1, wl = r0 + 32*(i&1)
    // B global: row = r0 + 32*i
    const __half* bG = g_Wt + (size_t)r0 * KTOT + fA * 8;

    // ---- ldmatrix lane constants ----
    const int rA   = (lane & 7) + ((lane >> 3) & 1) * 8;
    const int segA = lane >> 4;
    const uint32_t aXor = (uint32_t)(rA & 7) << 4;
    const int rB   = (lane & 7) + (((lane >> 4) & 1) ? 8 : 0);
    const int segB = (lane >> 3) & 1;
    const uint32_t bXor = (uint32_t)(rB & 7) << 4;

    int u0 = (bid * NU) / NCTA;
    const int u1 = ((bid + 1) * NU) / NCTA;

    while (u0 < u1) {
        const int tile = u0 / NIT;            // 0..127
        const int kt0  = u0 - tile * NIT;
        const int kend = min(u1 - tile * NIT, NIT);
        const int tn_  = tile >> 4;           // batch
        const int th0  = (tile & 15) << 2;    // 4 image rows
        const __half* aT = g_A + (size_t)(tn_ * HP + th0) * WP * CEXP
                         + (size_t)r0 * CEXP + fA * 8;   // row r0 base

        __syncthreads();   // previous segment's stages fully consumed

        float acc[4][8][4];
        #pragma unroll
        for (int mt = 0; mt < 4; mt++)
            #pragma unroll
            for (int nt = 0; nt < 8; nt++)
                #pragma unroll
                for (int q = 0; q < 4; q++) acc[mt][nt][q] = 0.0f;

        // ---- prologue: tiles kt0 (stage0), kt0+1 (stage1) ----
        #pragma unroll 1
        for (int pp = 0; pp < 2; ++pp) {
            int kp = kt0 + pp;
            if (kp < kend) {
                int tap = kp / NCH, ct = kp - tap * NCH;
                int koffA = ((tap / 3) * WP + (tap % 3)) * CEXP + ct * BKH;
                int koffB = tap * CEXP + ct * BKH;
                const uint32_t s0 = STG(pp);
                #pragma unroll
                for (int i = 0; i < 8; i++) {
                    const __half* src = aT + koffA
                        + ((i >> 1) * WP + (i & 1) * 32) * CEXP;
                    CP_ASYNC16(ldstA + s0 + i * 4096, src);
                }
                #pragma unroll
                for (int i = 0; i < 4; i++)
                    CP_ASYNC16(ldstB + s0 + i * 4096,
                               bG + koffB + (size_t)(i * 32) * KTOT);
            }
            CP_COMMIT();
        }

        int stage = 0;
        for (int kt = kt0; kt < kend; ++kt) {
            CP_WAIT(1);        // own group for tile kt complete
            __syncthreads();   // publish all threads' tile-kt data; compute
                               // kt-1 done -> stage (stage+2)%3 reusable

            if (kt + 2 < kend) {
                int kn = kt + 2;
                int tap = kn / NCH, ct = kn - tap * NCH;
                int koffA = ((tap / 3) * WP + (tap % 3)) * CEXP + ct * BKH;
                int koffB = tap * CEXP + ct * BKH;
                const uint32_t ns = STG((stage + 2) % 3);
                #pragma unroll
                for (int i = 0; i < 8; i++) {
                    const __half* src = aT + koffA
                        + ((i >> 1) * WP + (i & 1) * 32) * CEXP;
                    CP_ASYNC16(ldstA + ns + i * 4096, src);
                }
                #pragma unroll
                for (int i = 0; i < 4; i++)
                    CP_ASYNC16(ldstB + ns + i * 4096,
                               bG + koffB + (size_t)(i * 32) * KTOT);
            }
            CP_COMMIT();   // exactly one group per iteration

            const uint32_t Ab = sb + STG(stage);
            const uint32_t Bb = Ab + 32768;

            #pragma unroll
            for (int kk = 0; kk < 4; ++kk) {
                uint32_t afr[4][4];
                #pragma unroll
                for (int mt = 0; mt < 4; mt++) {
                    uint32_t addr = Ab + (uint32_t)(wm + mt * 16 + rA) * 128
                                  + (((uint32_t)(kk * 32 + segA * 16)) ^ aXor);
                    LDSM_X4(afr[mt], addr);
                }
                uint32_t bfr[4][4];
                #pragma unroll
                for (int np = 0; np < 4; np++) {
                    uint32_t addr = Bb + (uint32_t)(wn + np * 16 + rB) * 128
                                  + (((uint32_t)(kk * 32 + segB * 16)) ^ bXor);
                    LDSM_X4(bfr[np], addr);
                }
                #pragma unroll
                for (int np = 0; np < 4; np++)
                    #pragma unroll
                    for (int u = 0; u < 2; u++) {
                        const uint32_t bb0 = bfr[np][u * 2];
                        const uint32_t bb1 = bfr[np][u * 2 + 1];
                        #pragma unroll
                        for (int mt = 0; mt < 4; mt++) {
                            float* d = acc[mt][np * 2 + u];
                            asm volatile(
                                "mma.sync.aligned.m16n8k16.row.col.f32.f16.f16.f32 "
                                "{%0,%1,%2,%3}, {%4,%5,%6,%7}, {%8,%9}, {%0,%1,%2,%3};\n"
                                : "+f"(d[0]), "+f"(d[1]), "+f"(d[2]), "+f"(d[3])
                                : "r"(afr[mt][0]), "r"(afr[mt][1]),
                                  "r"(afr[mt][2]), "r"(afr[mt][3]),
                                  "r"(bb0), "r"(bb1));
                        }
                    }
            }
            stage = (stage + 1) % 3;
        }

        // ---- segment epilogue: red.add partials (bias once per tile) ----
        const float bsc = (kt0 == 0) ? 1.0f : 0.0f;
        #pragma unroll
        for (int nt = 0; nt < 8; nt++) {
            int col = wn + nt * 8 + tig * 2;
            float bx = bias[col] * bsc, by = bias[col + 1] * bsc;
            #pragma unroll
            for (int mt = 0; mt < 4; mt++) {
                int row0 = tile * 256 + wm + mt * 16 + gid;
                float* p0 = out + (size_t)row0 * COUT + col;
                float* p1 = out + (size_t)(row0 + 8) * COUT + col;
                RED_ADD_F32(p0,     acc[mt][nt][0] + bx);
                RED_ADD_F32(p0 + 1, acc[mt][nt][1] + by);
                RED_ADD_F32(p1,     acc[mt][nt][2] + bx);
                RED_ADD_F32(p1 + 1, acc[mt][nt][3] + by);
            }
        }

        u0 = tile * NIT + kend;
    }
}

// ---------------------------------------------------------------------------
extern "C" void kernel_launch(void* const* d_in, const int* in_sizes, int n_in,
                              void* d_out, int out_size) {
    const float* x        = (const float*)d_in[0];
    const float* base_w   = (const float*)d_in[1];
    const float* spline_w = (const float*)d_in[2];
    const float* bias     = (const float*)d_in[3];
    float* out = (float*)d_out;

    prep_kernel<<<NEXP + NWPK + NZERO, 256>>>(x, base_w, spline_w, out);
    cudaFuncSetAttribute(convkan_hmma,
                         cudaFuncAttributeMaxDynamicSharedMemorySize, SMEM_TOTAL);
    convkan_hmma<<<NCTA, 256, SMEM_TOTAL>>>(bias, out);
}